// round 16
// baseline (speedup 1.0000x reference)
#include <cuda_runtime.h>
#include <cuda_fp16.h>
#include <math.h>
#include <stdint.h>

// Problem constants
#define BB  8
#define SS  1024
#define EE  1024
#define HH  16
#define DD  64
#define FFF 4096
#define MM  (BB*SS)          // 8192 rows

// ---------------- scratch (static device globals; no cudaMalloc allowed) ----
__device__ __half g_xn  [(long long)MM*EE];
__device__ __half g_qkv [(long long)MM*3*EE];
__device__ __half g_ctx [(long long)MM*EE];
__device__ float  g_x1  [(long long)MM*EE];
__device__ __half g_h   [(long long)MM*FFF];
__device__ __half g_Wqkv[(long long)EE*3*EE];    // W_qkv [E, 3E] fp16 (q part pre-scaled)
__device__ float  g_bqkv[3*EE];
__device__ __half g_Wo  [(long long)EE*EE];
__device__ __half g_W1  [(long long)EE*FFF];
__device__ __half g_W2  [(long long)FFF*EE];

// 1/8 * log2(e): flash score scale, folded into Wq/bq at prep time
#define QSCALE 0.18033688011112042f

__device__ __forceinline__ uint32_t smem_u32(const void* p) {
    uint32_t a;
    asm("{ .reg .u64 t; cvta.to.shared.u64 t, %1; cvt.u32.u64 %0, t; }" : "=r"(a) : "l"(p));
    return a;
}
__device__ __forceinline__ void cp16(uint32_t dst, const void* src) {
    asm volatile("cp.async.cg.shared.global [%0], [%1], 16;" :: "r"(dst), "l"(src));
}
__device__ __forceinline__ void cp16ca(uint32_t dst, const void* src) {
    asm volatile("cp.async.ca.shared.global [%0], [%1], 16;" :: "r"(dst), "l"(src));
}
__device__ __forceinline__ void mma_f16(float* d, const uint32_t* a, const uint32_t* b) {
    asm volatile(
        "mma.sync.aligned.m16n8k16.row.col.f32.f16.f16.f32 "
        "{%0,%1,%2,%3}, {%4,%5,%6,%7}, {%8,%9}, {%0,%1,%2,%3};"
        : "+f"(d[0]), "+f"(d[1]), "+f"(d[2]), "+f"(d[3])
        : "r"(a[0]), "r"(a[1]), "r"(a[2]), "r"(a[3]), "r"(b[0]), "r"(b[1]));
}
__device__ __forceinline__ void ldm4(uint32_t& d0, uint32_t& d1, uint32_t& d2,
                                     uint32_t& d3, uint32_t addr) {
    asm volatile("ldmatrix.sync.aligned.m8n8.x4.shared.b16 {%0,%1,%2,%3}, [%4];"
                 : "=r"(d0), "=r"(d1), "=r"(d2), "=r"(d3) : "r"(addr));
}
__device__ __forceinline__ void ldm4t(uint32_t& d0, uint32_t& d1, uint32_t& d2,
                                      uint32_t& d3, uint32_t addr) {
    asm volatile("ldmatrix.sync.aligned.m8n8.x4.trans.shared.b16 {%0,%1,%2,%3}, [%4];"
                 : "=r"(d0), "=r"(d1), "=r"(d2), "=r"(d3) : "r"(addr));
}
__device__ __forceinline__ void ldm2t(uint32_t& d0, uint32_t& d1, uint32_t addr) {
    asm volatile("ldmatrix.sync.aligned.m8n8.x2.trans.shared.b16 {%0,%1}, [%2];"
                 : "=r"(d0), "=r"(d1) : "r"(addr));
}
__device__ __forceinline__ uint32_t packh2(float a, float b) {
    __half2 h = __floats2half2_rn(a, b);
    return *reinterpret_cast<uint32_t*>(&h);
}
__device__ __forceinline__ void ex2h2(uint32_t& v) {
    asm("ex2.approx.f16x2 %0, %0;" : "+r"(v));
}
__device__ __forceinline__ void pdl_wait() {
    asm volatile("griddepcontrol.wait;" ::: "memory");
}
__device__ __forceinline__ void pdl_trigger() {
    asm volatile("griddepcontrol.launch_dependents;" ::: "memory");
}

// ---------------- prep: Wq/Wk/Wv [H,E,D] -> Wqkv [E, 3E] (fp16) -------------
__global__ void repack16_k(const float* __restrict__ Wq, const float* __restrict__ Wk,
                           const float* __restrict__ Wv,
                           const float* __restrict__ bq, const float* __restrict__ bk,
                           const float* __restrict__ bv,
                           __half* __restrict__ Wt, float* __restrict__ bqkv) {
    int idx = blockIdx.x * blockDim.x + threadIdx.x;
    const int total = HH * EE * DD;
    if (idx < total) {
        int h = idx / (EE * DD);
        int e = (idx / DD) % EE;
        int d = idx % DD;
        int col = h * DD + d;
        long long dst = (long long)e * (3 * EE) + col;
        Wt[dst]          = __float2half_rn(Wq[idx] * QSCALE);
        Wt[dst + EE]     = __float2half_rn(Wk[idx]);
        Wt[dst + 2 * EE] = __float2half_rn(Wv[idx]);
    }
    if (idx < EE) {
        bqkv[idx]          = bq[idx] * QSCALE;
        bqkv[EE + idx]     = bk[idx];
        bqkv[2 * EE + idx] = bv[idx];
    }
}

// ---------------- prep: streaming fp32 -> fp16 convert (keeps layout) -------
__global__ void cvt16_k(const float* __restrict__ src, __half* __restrict__ dst, int n8) {
    int i = blockIdx.x * blockDim.x + threadIdx.x;
    if (i < n8) {
        float4 a = reinterpret_cast<const float4*>(src)[2 * i];
        float4 b = reinterpret_cast<const float4*>(src)[2 * i + 1];
        uint4 o;
        o.x = packh2(a.x, a.y); o.y = packh2(a.z, a.w);
        o.z = packh2(b.x, b.y); o.w = packh2(b.z, b.w);
        reinterpret_cast<uint4*>(dst)[i] = o;
    }
}

// ---------------- layernorm (fp16 out) ---------------------------------------
__global__ void layernorm_k(const float* __restrict__ x, const float* __restrict__ g,
                            const float* __restrict__ b, __half* __restrict__ y) {
    const float4* px = reinterpret_cast<const float4*>(x) + (long long)blockIdx.x * 256;
    uint2*        py = reinterpret_cast<uint2*>(y)        + (long long)blockIdx.x * 256;
    int tid = threadIdx.x;
    float4 v = px[tid];
    float s  = v.x + v.y + v.z + v.w;
    float sq = v.x*v.x + v.y*v.y + v.z*v.z + v.w*v.w;
    __shared__ float rs[8], rq[8];
    #pragma unroll
    for (int o = 16; o; o >>= 1) {
        s  += __shfl_xor_sync(~0u, s,  o);
        sq += __shfl_xor_sync(~0u, sq, o);
    }
    if ((tid & 31) == 0) { rs[tid >> 5] = s; rq[tid >> 5] = sq; }
    __syncthreads();
    float ts = 0.f, tq = 0.f;
    #pragma unroll
    for (int i = 0; i < 8; ++i) { ts += rs[i]; tq += rq[i]; }
    float mean = ts * (1.0f / EE);
    float var  = tq * (1.0f / EE) - mean * mean;
    float inv  = rsqrtf(var + 1e-5f);
    float4 gv = reinterpret_cast<const float4*>(g)[tid];
    float4 bv = reinterpret_cast<const float4*>(b)[tid];
    uint2 u;
    u.x = packh2((v.x - mean) * inv * gv.x + bv.x, (v.y - mean) * inv * gv.y + bv.y);
    u.y = packh2((v.z - mean) * inv * gv.z + bv.z, (v.w - mean) * inv * gv.w + bv.w);
    py[tid] = u;
}

// ---------------- fused flash attention (PDL-aware) --------------------------
#define HSTR 72
#define SM_FLASH (46080 * 2)

__global__ void __launch_bounds__(256)
flash_k(const __half* __restrict__ qkv, __half* __restrict__ ctx) {
    extern __shared__ char smraw[];
    __half* sm = reinterpret_cast<__half*>(smraw);
    const uint32_t s_base = smem_u32(sm);
    int tid = threadIdx.x, lane = tid & 31, warp = tid >> 5;
    int r = lane >> 2, q = lane & 3;
    int bh = blockIdx.y;
    int b = bh >> 4, h = bh & 15;
    int q0 = blockIdx.x * 128;
    int wr = warp * 16;

    // pre-wait work (own smem only): ones-column in V padding, all 4 buffers
    for (int i = tid; i < 4 * 64; i += 256) {
        int vb = i >> 6, row = i & 63;
        uint4* vp = reinterpret_cast<uint4*>(sm + 18432 + vb * 4608 + row * HSTR + 64);
        *vp = make_uint4(0x00003C00u, 0u, 0u, 0u);
    }
    pdl_wait();    // qkv (predecessor output) safe to read from here on

    const __half* Qg = qkv + ((long long)(b * SS + q0)) * (3 * EE) + h * DD;
    const __half* Kg = qkv + ((long long)(b * SS)) * (3 * EE) + EE + h * DD;
    const __half* Vg = Kg + EE;

    #pragma unroll
    for (int it = 0; it < 4; ++it) {
        int idx = tid + it * 256;
        int row = idx >> 3, ch = idx & 7;
        cp16(s_base + (uint32_t)((36864 + row * HSTR + ch * 8) * 2),
             Qg + (long long)row * (3 * EE) + ch * 8);
    }
    asm volatile("cp.async.commit_group;");

    auto load_pair = [&](int p) {
        #pragma unroll
        for (int half = 0; half < 2; ++half) {
            int i = 2 * p + half;
            int buf = i & 3;
            #pragma unroll
            for (int it = 0; it < 2; ++it) {
                int idx = tid + it * 256;
                int row = idx >> 3, ch = idx & 7;
                cp16(s_base + (uint32_t)((buf * 4608 + row * HSTR + ch * 8) * 2),
                     Kg + (long long)(i * 64 + row) * (3 * EE) + ch * 8);
            }
            #pragma unroll
            for (int it = 0; it < 2; ++it) {
                int idx = tid + it * 256;
                int row = idx >> 3, ch = idx & 7;
                cp16(s_base + (uint32_t)((18432 + buf * 4608 + row * HSTR + ch * 8) * 2),
                     Vg + (long long)(i * 64 + row) * (3 * EE) + ch * 8);
            }
        }
        asm volatile("cp.async.commit_group;");
    };
    load_pair(0);

    asm volatile("cp.async.wait_group 1;");
    __syncthreads();                 // cross-thread Q + padding visibility
    const uint32_t* Qsu = reinterpret_cast<const uint32_t*>(sm) + 18432;
    uint32_t qf[4][4];
    #pragma unroll
    for (int kk = 0; kk < 4; ++kk) {
        int base = (wr + r) * 36 + kk * 8 + q;
        qf[kk][0] = Qsu[base];
        qf[kk][1] = Qsu[base + 8 * 36];
        qf[kk][2] = Qsu[base + 4];
        qf[kk][3] = Qsu[base + 8 * 36 + 4];
    }

    float oacc[8][4];
    #pragma unroll
    for (int nt = 0; nt < 8; ++nt)
        #pragma unroll
        for (int c = 0; c < 4; ++c) oacc[nt][c] = 0.f;
    float lacc[4] = {0.f, 0.f, 0.f, 0.f};

    int gB = lane >> 3, liB = lane & 7;
    int mi = lane >> 3, rowin = lane & 7;
    int l16 = lane & 15;

    for (int p = 0; p < 8; ++p) {
        asm volatile("cp.async.wait_group 0;");
        __syncthreads();
        if (p < 7) load_pair(p + 1);

        #pragma unroll
        for (int sub = 0; sub < 2; ++sub) {
            int buf = (2 * p + sub) & 3;

            float sacc[8][4];
            #pragma unroll
            for (int nt = 0; nt < 8; ++nt)
                #pragma unroll
                for (int c = 0; c < 4; ++c) sacc[nt][c] = 0.f;
            #pragma unroll
            for (int kk = 0; kk < 4; ++kk) {
                #pragma unroll
                for (int pp = 0; pp < 4; ++pp) {
                    uint32_t rowB = (uint32_t)(pp * 16 + ((gB >> 1) << 3) + liB);
                    uint32_t kb   = (uint32_t)(kk * 16 + ((gB & 1) << 3));
                    uint32_t d0, d1, d2, d3;
                    ldm4(d0, d1, d2, d3,
                         s_base + (uint32_t)((buf * 4608 + rowB * HSTR + kb) * 2));
                    uint32_t bA[2] = { d0, d1 };
                    uint32_t bB[2] = { d2, d3 };
                    mma_f16(sacc[2*pp],     qf[kk], bA);
                    mma_f16(sacc[2*pp + 1], qf[kk], bB);
                }
            }

            uint32_t pf[4][4];
            #pragma unroll
            for (int kk = 0; kk < 4; ++kk) {
                pf[kk][0] = packh2(sacc[2*kk][0],   sacc[2*kk][1]);
                pf[kk][1] = packh2(sacc[2*kk][2],   sacc[2*kk][3]);
                pf[kk][2] = packh2(sacc[2*kk+1][0], sacc[2*kk+1][1]);
                pf[kk][3] = packh2(sacc[2*kk+1][2], sacc[2*kk+1][3]);
                ex2h2(pf[kk][0]); ex2h2(pf[kk][1]);
                ex2h2(pf[kk][2]); ex2h2(pf[kk][3]);
            }

            #pragma unroll
            for (int kk = 0; kk < 4; ++kk) {
                #pragma unroll
                for (int nbp = 0; nbp < 4; ++nbp) {
                    uint32_t vaddr = s_base +
                        (uint32_t)((18432 + buf * 4608 +
                                    (kk * 16 + ((mi & 1) << 3) + rowin) * HSTR +
                                    nbp * 16 + ((mi >> 1) << 3)) * 2);
                    uint32_t d0, d1, d2, d3;
                    ldm4t(d0, d1, d2, d3, vaddr);
                    uint32_t bA[2] = { d0, d1 };
                    uint32_t bB[2] = { d2, d3 };
                    mma_f16(oacc[2*nbp],     pf[kk], bA);
                    mma_f16(oacc[2*nbp + 1], pf[kk], bB);
                }
                uint32_t e0, e1;
                ldm2t(e0, e1,
                      s_base + (uint32_t)((18432 + buf * 4608 +
                                           (kk * 16 + l16) * HSTR + 64) * 2));
                uint32_t bl[2] = { e0, e1 };
                mma_f16(lacc, pf[kk], bl);
            }
        }
    }

    pdl_trigger();   // successor (Wo GEMM) may start its weight prefetch

    int srcl = lane & ~3;
    float l0 = __shfl_sync(~0u, lacc[0], srcl);
    float l1 = __shfl_sync(~0u, lacc[2], srcl);
    float inv0 = 1.f / l0, inv1 = 1.f / l1;
    long long grow0 = (long long)(b * SS + q0 + wr + r) * EE + h * DD;
    long long grow1 = grow0 + 8LL * EE;
    #pragma unroll
    for (int nt = 0; nt < 8; ++nt) {
        int col = nt * 8 + 2 * q;
        *reinterpret_cast<uint32_t*>(&ctx[grow0 + col]) =
            packh2(oacc[nt][0] * inv0, oacc[nt][1] * inv0);
        *reinterpret_cast<uint32_t*>(&ctx[grow1 + col]) =
            packh2(oacc[nt][2] * inv1, oacc[nt][3] * inv1);
    }
}

// ---------------- fp16 tensor-core GEMM (PDL: B prefetch pre-wait) -----------
#define GSTR  72
#define BSTRN 136
#define ASTG  9216
#define BSTG  8704
#define BBASE (3 * ASTG)
#define SM_DENSE ((3 * ASTG + 3 * BSTG) * 2)   // 107520 B -> 2 CTA/SM

template<int ACT, int OUTH>
__global__ void __launch_bounds__(256)
mma_gemm(const __half* __restrict__ A, const __half* __restrict__ B,
         const float* __restrict__ bias, const float* __restrict__ Res,
         void* __restrict__ Cv, int K, int ldb, int ldc) {
    extern __shared__ char smraw[];
    __half* sm = reinterpret_cast<__half*>(smraw);
    const uint32_t s_base = smem_u32(sm);

    int tid  = threadIdx.x;
    int lane = tid & 31;
    int warp = tid >> 5;
    int wm   = (warp & 3) * 32;
    int wn   = (warp >> 2) * 64;
    int m0   = blockIdx.y * 128;
    int n0   = blockIdx.x * 128;
    int r    = lane >> 2;
    int q    = lane & 3;

    float acc[2][8][4];
    #pragma unroll
    for (int i = 0; i < 2; ++i)
        #pragma unroll
        for (int j = 0; j < 8; ++j)
            #pragma unroll
            for (int t = 0; t < 4; ++t) acc[i][j][t] = 0.f;

    auto load_A = [&](int s, int st) {
        int k0 = s * 64;
        #pragma unroll
        for (int it = 0; it < 4; ++it) {
            int idx = tid + it * 256;
            int row = idx >> 3, ch = idx & 7;
            cp16ca(s_base + (uint32_t)((st * ASTG + row * GSTR + ch * 8) * 2),
                   A + (long long)(m0 + row) * K + k0 + ch * 8);
        }
    };
    auto load_B = [&](int s, int st) {
        int k0 = s * 64;
        #pragma unroll
        for (int it = 0; it < 4; ++it) {
            int idx = tid + it * 256;
            int row = idx >> 4, ch = idx & 15;
            cp16(s_base + (uint32_t)((BBASE + st * BSTG + row * BSTRN + ch * 8) * 2),
                 B + (long long)(k0 + row) * ldb + n0 + ch * 8);
        }
    };

    int slabs = K / 64;
    // B (weights) is independent of the predecessor: prefetch BEFORE the
    // grid-dependency wait so it overlaps the predecessor's epilogue/tail.
    load_B(0, 0); load_B(1, 1);
    asm volatile("cp.async.commit_group;");
    pdl_wait();
    load_A(0, 0); load_A(1, 1);
    asm volatile("cp.async.commit_group;");

    int rA = lane & 15, cA = (lane >> 4) << 3;
    int mi = lane >> 3, rowin = lane & 7;

    for (int s = 0; s < slabs; ++s) {
        if (s == 0 || s + 1 >= slabs) asm volatile("cp.async.wait_group 0;");
        else                          asm volatile("cp.async.wait_group 1;");
        __syncthreads();
        if (s + 2 < slabs) {
            load_A(s + 2, (s + 2) % 3);
            load_B(s + 2, (s + 2) % 3);
            asm volatile("cp.async.commit_group;");
        }

        int st = s % 3;
        uint32_t aBase = s_base + (uint32_t)(st * ASTG * 2);
        uint32_t bBase = s_base + (uint32_t)((BBASE + st * BSTG) * 2);
        #pragma unroll
        for (int kk = 0; kk < 4; ++kk) {
            uint32_t af[2][4];
            #pragma unroll
            for (int mt = 0; mt < 2; ++mt)
                ldm4(af[mt][0], af[mt][1], af[mt][2], af[mt][3],
                     aBase + (uint32_t)(((wm + mt * 16 + rA) * GSTR + kk * 16 + cA) * 2));
            #pragma unroll
            for (int p = 0; p < 4; ++p) {
                uint32_t d0, d1, d2, d3;
                ldm4t(d0, d1, d2, d3,
                      bBase + (uint32_t)(((kk * 16 + ((mi & 1) << 3) + rowin) * BSTRN
                                          + wn + p * 16 + ((mi >> 1) << 3)) * 2));
                uint32_t bA[2] = { d0, d1 };
                uint32_t bB[2] = { d2, d3 };
                #pragma unroll
                for (int mt = 0; mt < 2; ++mt) {
                    mma_f16(acc[mt][2*p],     af[mt], bA);
                    mma_f16(acc[mt][2*p + 1], af[mt], bB);
                }
            }
        }
    }

    pdl_trigger();   // successor may start its independent prefetch now

    #pragma unroll
    for (int mt = 0; mt < 2; ++mt) {
        #pragma unroll
        for (int nt = 0; nt < 8; ++nt) {
            long long row = m0 + wm + mt * 16 + r;
            int col = n0 + wn + nt * 8 + 2 * q;
            float2 v0 = make_float2(acc[mt][nt][0], acc[mt][nt][1]);
            float2 v1 = make_float2(acc[mt][nt][2], acc[mt][nt][3]);
            if (bias) {
                float2 bb = *reinterpret_cast<const float2*>(&bias[col]);
                v0.x += bb.x; v0.y += bb.y; v1.x += bb.x; v1.y += bb.y;
            }
            if (Res) {
                float2 r0 = *reinterpret_cast<const float2*>(&Res[row * ldc + col]);
                float2 r1 = *reinterpret_cast<const float2*>(&Res[(row + 8) * ldc + col]);
                v0.x += r0.x; v0.y += r0.y; v1.x += r1.x; v1.y += r1.y;
            }
            if (ACT == 1) {
                v0.x = 0.5f * v0.x * (1.0f + erff(v0.x * 0.70710678118654752f));
                v0.y = 0.5f * v0.y * (1.0f + erff(v0.y * 0.70710678118654752f));
                v1.x = 0.5f * v1.x * (1.0f + erff(v1.x * 0.70710678118654752f));
                v1.y = 0.5f * v1.y * (1.0f + erff(v1.y * 0.70710678118654752f));
            }
            if (OUTH) {
                __half* C = reinterpret_cast<__half*>(Cv);
                *reinterpret_cast<uint32_t*>(&C[row * ldc + col])       = packh2(v0.x, v0.y);
                *reinterpret_cast<uint32_t*>(&C[(row + 8) * ldc + col]) = packh2(v1.x, v1.y);
            } else {
                float* C = reinterpret_cast<float*>(Cv);
                *reinterpret_cast<float2*>(&C[row * ldc + col])       = v0;
                *reinterpret_cast<float2*>(&C[(row + 8) * ldc + col]) = v1;
            }
        }
    }
}

// ---------------- launcher ---------------------------------------------------
extern "C" void kernel_launch(void* const* d_in, const int* in_sizes, int n_in,
                              void* d_out, int out_size) {
    const float* x     = (const float*)d_in[0];
    const float* Wq    = (const float*)d_in[1];
    const float* bq    = (const float*)d_in[2];
    const float* Wk    = (const float*)d_in[3];
    const float* bk    = (const float*)d_in[4];
    const float* Wv    = (const float*)d_in[5];
    const float* bv    = (const float*)d_in[6];
    const float* Wo    = (const float*)d_in[7];
    const float* bo    = (const float*)d_in[8];
    const float* g1    = (const float*)d_in[9];
    const float* beta1 = (const float*)d_in[10];
    const float* g2    = (const float*)d_in[11];
    const float* beta2 = (const float*)d_in[12];
    const float* W1    = (const float*)d_in[13];
    const float* c1    = (const float*)d_in[14];
    const float* W2    = (const float*)d_in[15];
    const float* c2    = (const float*)d_in[16];
    float* out = (float*)d_out;

    __half *xn, *qkv, *ctx, *hb, *Wqkv16, *Wo16, *W116, *W216;
    float *x1, *bqkv;
    cudaGetSymbolAddress((void**)&xn,     g_xn);
    cudaGetSymbolAddress((void**)&qkv,    g_qkv);
    cudaGetSymbolAddress((void**)&ctx,    g_ctx);
    cudaGetSymbolAddress((void**)&x1,     g_x1);
    cudaGetSymbolAddress((void**)&hb,     g_h);
    cudaGetSymbolAddress((void**)&Wqkv16, g_Wqkv);
    cudaGetSymbolAddress((void**)&bqkv,   g_bqkv);
    cudaGetSymbolAddress((void**)&Wo16,   g_Wo);
    cudaGetSymbolAddress((void**)&W116,   g_W1);
    cudaGetSymbolAddress((void**)&W216,   g_W2);

    static bool attr_done = false;
    static cudaStream_t s1 = nullptr, s2 = nullptr;
    static cudaEvent_t eF1, eF2, eJ1, eJ2;
    if (!attr_done) {
        cudaFuncSetAttribute((const void*)mma_gemm<0,1>,
                             cudaFuncAttributeMaxDynamicSharedMemorySize, SM_DENSE);
        cudaFuncSetAttribute((const void*)mma_gemm<0,0>,
                             cudaFuncAttributeMaxDynamicSharedMemorySize, SM_DENSE);
        cudaFuncSetAttribute((const void*)mma_gemm<1,1>,
                             cudaFuncAttributeMaxDynamicSharedMemorySize, SM_DENSE);
        cudaFuncSetAttribute((const void*)flash_k,
                             cudaFuncAttributeMaxDynamicSharedMemorySize, SM_FLASH);
        cudaStreamCreateWithFlags(&s1, cudaStreamNonBlocking);
        cudaStreamCreateWithFlags(&s2, cudaStreamNonBlocking);
        cudaEventCreateWithFlags(&eF1, cudaEventDisableTiming);
        cudaEventCreateWithFlags(&eF2, cudaEventDisableTiming);
        cudaEventCreateWithFlags(&eJ1, cudaEventDisableTiming);
        cudaEventCreateWithFlags(&eJ2, cudaEventDisableTiming);
        attr_done = true;
    }

    // PDL launch config (programmatic stream serialization)
    cudaLaunchAttribute pdlAttr[1];
    pdlAttr[0].id = cudaLaunchAttributeProgrammaticStreamSerialization;
    pdlAttr[0].val.programmaticStreamSerializationAllowed = 1;

    auto gemm_cfg = [&]() {
        cudaLaunchConfig_t cfg = {};
        cfg.blockDim = dim3(256, 1, 1);
        cfg.dynamicSmemBytes = SM_DENSE;
        cfg.stream = 0;
        cfg.attrs = pdlAttr;
        cfg.numAttrs = 1;
        return cfg;
    };

    // 0) weight prep, forked onto side streams (capture-safe fork-join)
    cudaEventRecord(eF1, 0);
    cudaStreamWaitEvent(s1, eF1, 0);
    repack16_k<<<(HH * EE * DD + 255) / 256, 256, 0, s1>>>(
        Wq, Wk, Wv, bq, bk, bv, Wqkv16, bqkv);
    cudaEventRecord(eJ1, s1);

    cudaEventRecord(eF2, 0);
    cudaStreamWaitEvent(s2, eF2, 0);
    cvt16_k<<<(EE*EE/8  + 255) / 256, 256, 0, s2>>>(Wo, Wo16, EE*EE/8);
    cvt16_k<<<(EE*FFF/8 + 255) / 256, 256, 0, s2>>>(W1, W116, EE*FFF/8);
    cvt16_k<<<(FFF*EE/8 + 255) / 256, 256, 0, s2>>>(W2, W216, FFF*EE/8);
    cudaEventRecord(eJ2, s2);

    // 1) LN1 -> fp16 (parallel with prep)
    layernorm_k<<<MM, 256>>>(x, g1, beta1, xn);

    // join repack before QKV
    cudaStreamWaitEvent(0, eJ1, 0);

    // 2) QKV projection -> fp16 (PDL)
    {
        cudaLaunchConfig_t cfg = gemm_cfg();
        cfg.gridDim = dim3(3*EE/128, MM/128, 1);
        cudaLaunchKernelEx(&cfg, mma_gemm<0,1>,
            (const __half*)xn, (const __half*)Wqkv16, (const float*)bqkv,
            (const float*)nullptr, (void*)qkv, (int)EE, (int)(3*EE), (int)(3*EE));
    }

    // 3) flash attention -> ctx (PDL: launches during QKV epilogue)
    {
        cudaLaunchConfig_t cfg = gemm_cfg();
        cfg.gridDim = dim3(SS/128, BB*HH, 1);
        cfg.dynamicSmemBytes = SM_FLASH;
        cudaLaunchKernelEx(&cfg, flash_k, (const __half*)qkv, (__half*)ctx);
    }

    // join converts before they are consumed
    cudaStreamWaitEvent(0, eJ2, 0);

    // 4) out-proj + bias + residual -> x1 (PDL)
    {
        cudaLaunchConfig_t cfg = gemm_cfg();
        cfg.gridDim = dim3(EE/128, MM/128, 1);
        cudaLaunchKernelEx(&cfg, mma_gemm<0,0>,
            (const __half*)ctx, (const __half*)Wo16, (const float*)bo,
            (const float*)x, (void*)x1, (int)EE, (int)EE, (int)EE);
    }

    // 5) LN2 -> fp16 (normal launch: full dependency on Wo)
    layernorm_k<<<MM, 256>>>(x1, g2, beta2, xn);

    // 6) MLP up + exact GELU -> fp16 (PDL)
    {
        cudaLaunchConfig_t cfg = gemm_cfg();
        cfg.gridDim = dim3(FFF/128, MM/128, 1);
        cudaLaunchKernelEx(&cfg, mma_gemm<1,1>,
            (const __half*)xn, (const __half*)W116, (const float*)c1,
            (const float*)nullptr, (void*)hb, (int)EE, (int)FFF, (int)FFF);
    }

    // 7) MLP down + bias + residual -> d_out (PDL: W2 prefetch overlaps
    //    MLP-up's 64MB epilogue stores)
    {
        cudaLaunchConfig_t cfg = gemm_cfg();
        cfg.gridDim = dim3(EE/128, MM/128, 1);
        cudaLaunchKernelEx(&cfg, mma_gemm<0,0>,
            (const __half*)hb, (const __half*)W216, (const float*)c2,
            (const float*)x1, (void*)out, (int)FFF, (int)EE, (int)EE);
    }
}

// round 17
// speedup vs baseline: 1.0262x; 1.0262x over previous
#include <cuda_runtime.h>
#include <cuda_fp16.h>
#include <math.h>
#include <stdint.h>

// Problem constants
#define BB  8
#define SS  1024
#define EE  1024
#define HH  16
#define DD  64
#define FFF 4096
#define MM  (BB*SS)          // 8192 rows

// ---------------- scratch (static device globals; no cudaMalloc allowed) ----
__device__ __half g_xn  [(long long)MM*EE];
__device__ __half g_qkv [(long long)MM*3*EE];
__device__ __half g_ctx [(long long)MM*EE];
__device__ float  g_x1  [(long long)MM*EE];
__device__ __half g_h   [(long long)MM*FFF];
__device__ __half g_Wqkv[(long long)EE*3*EE];    // W_qkv [E, 3E] fp16 (q part pre-scaled)
__device__ float  g_bqkv[3*EE];
__device__ __half g_Wo  [(long long)EE*EE];
__device__ __half g_W1  [(long long)EE*FFF];
__device__ __half g_W2  [(long long)FFF*EE];

// 1/8 * log2(e): flash score scale, folded into Wq/bq at prep time
#define QSCALE 0.18033688011112042f

__device__ __forceinline__ uint32_t smem_u32(const void* p) {
    uint32_t a;
    asm("{ .reg .u64 t; cvta.to.shared.u64 t, %1; cvt.u32.u64 %0, t; }" : "=r"(a) : "l"(p));
    return a;
}
__device__ __forceinline__ void cp16(uint32_t dst, const void* src) {
    asm volatile("cp.async.cg.shared.global [%0], [%1], 16;" :: "r"(dst), "l"(src));
}
__device__ __forceinline__ void cp16ca(uint32_t dst, const void* src) {
    asm volatile("cp.async.ca.shared.global [%0], [%1], 16;" :: "r"(dst), "l"(src));
}
__device__ __forceinline__ void mma_f16(float* d, const uint32_t* a, const uint32_t* b) {
    asm volatile(
        "mma.sync.aligned.m16n8k16.row.col.f32.f16.f16.f32 "
        "{%0,%1,%2,%3}, {%4,%5,%6,%7}, {%8,%9}, {%0,%1,%2,%3};"
        : "+f"(d[0]), "+f"(d[1]), "+f"(d[2]), "+f"(d[3])
        : "r"(a[0]), "r"(a[1]), "r"(a[2]), "r"(a[3]), "r"(b[0]), "r"(b[1]));
}
__device__ __forceinline__ void ldm4(uint32_t& d0, uint32_t& d1, uint32_t& d2,
                                     uint32_t& d3, uint32_t addr) {
    asm volatile("ldmatrix.sync.aligned.m8n8.x4.shared.b16 {%0,%1,%2,%3}, [%4];"
                 : "=r"(d0), "=r"(d1), "=r"(d2), "=r"(d3) : "r"(addr));
}
__device__ __forceinline__ void ldm4t(uint32_t& d0, uint32_t& d1, uint32_t& d2,
                                      uint32_t& d3, uint32_t addr) {
    asm volatile("ldmatrix.sync.aligned.m8n8.x4.trans.shared.b16 {%0,%1,%2,%3}, [%4];"
                 : "=r"(d0), "=r"(d1), "=r"(d2), "=r"(d3) : "r"(addr));
}
__device__ __forceinline__ void ldm2t(uint32_t& d0, uint32_t& d1, uint32_t addr) {
    asm volatile("ldmatrix.sync.aligned.m8n8.x2.trans.shared.b16 {%0,%1}, [%2];"
                 : "=r"(d0), "=r"(d1) : "r"(addr));
}
__device__ __forceinline__ uint32_t packh2(float a, float b) {
    __half2 h = __floats2half2_rn(a, b);
    return *reinterpret_cast<uint32_t*>(&h);
}
__device__ __forceinline__ void ex2h2(uint32_t& v) {
    asm("ex2.approx.f16x2 %0, %0;" : "+r"(v));
}
// fast GELU: x * sigmoid(1.59577(x + 0.044715 x^3))  (tanh-form rewritten)
__device__ __forceinline__ float gelu_f(float x) {
    float u = x * fmaf(0.07135481627f, x * x, 1.5957691216f);
    float e = __expf(-u);
    return __fdividef(x, 1.0f + e);
}

// ---------------- prep: Wq/Wk/Wv [H,E,D] -> Wqkv [E, 3E] (fp16) -------------
__global__ void repack16_k(const float* __restrict__ Wq, const float* __restrict__ Wk,
                           const float* __restrict__ Wv,
                           const float* __restrict__ bq, const float* __restrict__ bk,
                           const float* __restrict__ bv,
                           __half* __restrict__ Wt, float* __restrict__ bqkv) {
    int idx = blockIdx.x * blockDim.x + threadIdx.x;
    const int total = HH * EE * DD;
    if (idx < total) {
        int h = idx / (EE * DD);
        int e = (idx / DD) % EE;
        int d = idx % DD;
        int col = h * DD + d;
        long long dst = (long long)e * (3 * EE) + col;
        Wt[dst]          = __float2half_rn(Wq[idx] * QSCALE);
        Wt[dst + EE]     = __float2half_rn(Wk[idx]);
        Wt[dst + 2 * EE] = __float2half_rn(Wv[idx]);
    }
    if (idx < EE) {
        bqkv[idx]          = bq[idx] * QSCALE;
        bqkv[EE + idx]     = bk[idx];
        bqkv[2 * EE + idx] = bv[idx];
    }
}

// ---------------- prep: streaming fp32 -> fp16 convert (keeps layout) -------
__global__ void cvt16_k(const float* __restrict__ src, __half* __restrict__ dst, int n8) {
    int i = blockIdx.x * blockDim.x + threadIdx.x;
    if (i < n8) {
        float4 a = reinterpret_cast<const float4*>(src)[2 * i];
        float4 b = reinterpret_cast<const float4*>(src)[2 * i + 1];
        uint4 o;
        o.x = packh2(a.x, a.y); o.y = packh2(a.z, a.w);
        o.z = packh2(b.x, b.y); o.w = packh2(b.z, b.w);
        reinterpret_cast<uint4*>(dst)[i] = o;
    }
}

// ---------------- layernorm (fp16 out) ---------------------------------------
__global__ void layernorm_k(const float* __restrict__ x, const float* __restrict__ g,
                            const float* __restrict__ b, __half* __restrict__ y) {
    const float4* px = reinterpret_cast<const float4*>(x) + (long long)blockIdx.x * 256;
    uint2*        py = reinterpret_cast<uint2*>(y)        + (long long)blockIdx.x * 256;
    int tid = threadIdx.x;
    float4 v = px[tid];
    float s  = v.x + v.y + v.z + v.w;
    float sq = v.x*v.x + v.y*v.y + v.z*v.z + v.w*v.w;
    __shared__ float rs[8], rq[8];
    #pragma unroll
    for (int o = 16; o; o >>= 1) {
        s  += __shfl_xor_sync(~0u, s,  o);
        sq += __shfl_xor_sync(~0u, sq, o);
    }
    if ((tid & 31) == 0) { rs[tid >> 5] = s; rq[tid >> 5] = sq; }
    __syncthreads();
    float ts = 0.f, tq = 0.f;
    #pragma unroll
    for (int i = 0; i < 8; ++i) { ts += rs[i]; tq += rq[i]; }
    float mean = ts * (1.0f / EE);
    float var  = tq * (1.0f / EE) - mean * mean;
    float inv  = rsqrtf(var + 1e-5f);
    float4 gv = reinterpret_cast<const float4*>(g)[tid];
    float4 bv = reinterpret_cast<const float4*>(b)[tid];
    uint2 u;
    u.x = packh2((v.x - mean) * inv * gv.x + bv.x, (v.y - mean) * inv * gv.y + bv.y);
    u.y = packh2((v.z - mean) * inv * gv.z + bv.z, (v.w - mean) * inv * gv.w + bv.w);
    py[tid] = u;
}

// ---------------- fused flash attention (R15 version, no PDL) ----------------
#define HSTR 72
#define SM_FLASH (46080 * 2)

__global__ void __launch_bounds__(256)
flash_k(const __half* __restrict__ qkv, __half* __restrict__ ctx) {
    extern __shared__ char smraw[];
    __half* sm = reinterpret_cast<__half*>(smraw);
    const uint32_t s_base = smem_u32(sm);
    int tid = threadIdx.x, lane = tid & 31, warp = tid >> 5;
    int r = lane >> 2, q = lane & 3;
    int bh = blockIdx.y;
    int b = bh >> 4, h = bh & 15;
    int q0 = blockIdx.x * 128;
    int wr = warp * 16;

    const __half* Qg = qkv + ((long long)(b * SS + q0)) * (3 * EE) + h * DD;
    const __half* Kg = qkv + ((long long)(b * SS)) * (3 * EE) + EE + h * DD;
    const __half* Vg = Kg + EE;

    #pragma unroll
    for (int it = 0; it < 4; ++it) {
        int idx = tid + it * 256;
        int row = idx >> 3, ch = idx & 7;
        cp16(s_base + (uint32_t)((36864 + row * HSTR + ch * 8) * 2),
             Qg + (long long)row * (3 * EE) + ch * 8);
    }
    asm volatile("cp.async.commit_group;");

    auto load_pair = [&](int p) {
        #pragma unroll
        for (int half = 0; half < 2; ++half) {
            int i = 2 * p + half;
            int buf = i & 3;
            #pragma unroll
            for (int it = 0; it < 2; ++it) {
                int idx = tid + it * 256;
                int row = idx >> 3, ch = idx & 7;
                cp16(s_base + (uint32_t)((buf * 4608 + row * HSTR + ch * 8) * 2),
                     Kg + (long long)(i * 64 + row) * (3 * EE) + ch * 8);
            }
            #pragma unroll
            for (int it = 0; it < 2; ++it) {
                int idx = tid + it * 256;
                int row = idx >> 3, ch = idx & 7;
                cp16(s_base + (uint32_t)((18432 + buf * 4608 + row * HSTR + ch * 8) * 2),
                     Vg + (long long)(i * 64 + row) * (3 * EE) + ch * 8);
            }
        }
        asm volatile("cp.async.commit_group;");
    };
    load_pair(0);

    for (int i = tid; i < 4 * 64; i += 256) {
        int vb = i >> 6, row = i & 63;
        uint4* vp = reinterpret_cast<uint4*>(sm + 18432 + vb * 4608 + row * HSTR + 64);
        *vp = make_uint4(0x00003C00u, 0u, 0u, 0u);
    }

    asm volatile("cp.async.wait_group 1;");
    __syncthreads();                 // cross-thread Q + padding visibility
    const uint32_t* Qsu = reinterpret_cast<const uint32_t*>(sm) + 18432;
    uint32_t qf[4][4];
    #pragma unroll
    for (int kk = 0; kk < 4; ++kk) {
        int base = (wr + r) * 36 + kk * 8 + q;
        qf[kk][0] = Qsu[base];
        qf[kk][1] = Qsu[base + 8 * 36];
        qf[kk][2] = Qsu[base + 4];
        qf[kk][3] = Qsu[base + 8 * 36 + 4];
    }

    float oacc[8][4];
    #pragma unroll
    for (int nt = 0; nt < 8; ++nt)
        #pragma unroll
        for (int c = 0; c < 4; ++c) oacc[nt][c] = 0.f;
    float lacc[4] = {0.f, 0.f, 0.f, 0.f};

    int gB = lane >> 3, liB = lane & 7;
    int mi = lane >> 3, rowin = lane & 7;
    int l16 = lane & 15;

    for (int p = 0; p < 8; ++p) {
        asm volatile("cp.async.wait_group 0;");
        __syncthreads();
        if (p < 7) load_pair(p + 1);

        #pragma unroll
        for (int sub = 0; sub < 2; ++sub) {
            int buf = (2 * p + sub) & 3;

            float sacc[8][4];
            #pragma unroll
            for (int nt = 0; nt < 8; ++nt)
                #pragma unroll
                for (int c = 0; c < 4; ++c) sacc[nt][c] = 0.f;
            #pragma unroll
            for (int kk = 0; kk < 4; ++kk) {
                #pragma unroll
                for (int pp = 0; pp < 4; ++pp) {
                    uint32_t rowB = (uint32_t)(pp * 16 + ((gB >> 1) << 3) + liB);
                    uint32_t kb   = (uint32_t)(kk * 16 + ((gB & 1) << 3));
                    uint32_t d0, d1, d2, d3;
                    ldm4(d0, d1, d2, d3,
                         s_base + (uint32_t)((buf * 4608 + rowB * HSTR + kb) * 2));
                    uint32_t bA[2] = { d0, d1 };
                    uint32_t bB[2] = { d2, d3 };
                    mma_f16(sacc[2*pp],     qf[kk], bA);
                    mma_f16(sacc[2*pp + 1], qf[kk], bB);
                }
            }

            uint32_t pf[4][4];
            #pragma unroll
            for (int kk = 0; kk < 4; ++kk) {
                pf[kk][0] = packh2(sacc[2*kk][0],   sacc[2*kk][1]);
                pf[kk][1] = packh2(sacc[2*kk][2],   sacc[2*kk][3]);
                pf[kk][2] = packh2(sacc[2*kk+1][0], sacc[2*kk+1][1]);
                pf[kk][3] = packh2(sacc[2*kk+1][2], sacc[2*kk+1][3]);
                ex2h2(pf[kk][0]); ex2h2(pf[kk][1]);
                ex2h2(pf[kk][2]); ex2h2(pf[kk][3]);
            }

            #pragma unroll
            for (int kk = 0; kk < 4; ++kk) {
                #pragma unroll
                for (int nbp = 0; nbp < 4; ++nbp) {
                    uint32_t vaddr = s_base +
                        (uint32_t)((18432 + buf * 4608 +
                                    (kk * 16 + ((mi & 1) << 3) + rowin) * HSTR +
                                    nbp * 16 + ((mi >> 1) << 3)) * 2);
                    uint32_t d0, d1, d2, d3;
                    ldm4t(d0, d1, d2, d3, vaddr);
                    uint32_t bA[2] = { d0, d1 };
                    uint32_t bB[2] = { d2, d3 };
                    mma_f16(oacc[2*nbp],     pf[kk], bA);
                    mma_f16(oacc[2*nbp + 1], pf[kk], bB);
                }
                uint32_t e0, e1;
                ldm2t(e0, e1,
                      s_base + (uint32_t)((18432 + buf * 4608 +
                                           (kk * 16 + l16) * HSTR + 64) * 2));
                uint32_t bl[2] = { e0, e1 };
                mma_f16(lacc, pf[kk], bl);
            }
        }
    }

    int srcl = lane & ~3;
    float l0 = __shfl_sync(~0u, lacc[0], srcl);
    float l1 = __shfl_sync(~0u, lacc[2], srcl);
    float inv0 = 1.f / l0, inv1 = 1.f / l1;
    long long grow0 = (long long)(b * SS + q0 + wr + r) * EE + h * DD;
    long long grow1 = grow0 + 8LL * EE;
    #pragma unroll
    for (int nt = 0; nt < 8; ++nt) {
        int col = nt * 8 + 2 * q;
        *reinterpret_cast<uint32_t*>(&ctx[grow0 + col]) =
            packh2(oacc[nt][0] * inv0, oacc[nt][1] * inv0);
        *reinterpret_cast<uint32_t*>(&ctx[grow1 + col]) =
            packh2(oacc[nt][2] * inv1, oacc[nt][3] * inv1);
    }
}

// ---------------- fp16 tensor-core GEMM (R15 version, fast GELU) -------------
#define GSTR  72
#define BSTRN 136
#define ASTG  9216
#define BSTG  8704
#define BBASE (3 * ASTG)
#define SM_DENSE ((3 * ASTG + 3 * BSTG) * 2)   // 107520 B -> 2 CTA/SM

template<int ACT, int OUTH>
__global__ void __launch_bounds__(256)
mma_gemm(const __half* __restrict__ A, const __half* __restrict__ B,
         const float* __restrict__ bias, const float* __restrict__ Res,
         void* __restrict__ Cv, int K, int ldb, int ldc) {
    extern __shared__ char smraw[];
    __half* sm = reinterpret_cast<__half*>(smraw);
    const uint32_t s_base = smem_u32(sm);

    int tid  = threadIdx.x;
    int lane = tid & 31;
    int warp = tid >> 5;
    int wm   = (warp & 3) * 32;
    int wn   = (warp >> 2) * 64;
    int m0   = blockIdx.y * 128;
    int n0   = blockIdx.x * 128;
    int r    = lane >> 2;
    int q    = lane & 3;

    float acc[2][8][4];
    #pragma unroll
    for (int i = 0; i < 2; ++i)
        #pragma unroll
        for (int j = 0; j < 8; ++j)
            #pragma unroll
            for (int t = 0; t < 4; ++t) acc[i][j][t] = 0.f;

    auto load_tiles = [&](int s, int st) {
        int k0 = s * 64;
        #pragma unroll
        for (int it = 0; it < 4; ++it) {
            int idx = tid + it * 256;
            int row = idx >> 3, ch = idx & 7;
            cp16ca(s_base + (uint32_t)((st * ASTG + row * GSTR + ch * 8) * 2),
                   A + (long long)(m0 + row) * K + k0 + ch * 8);
        }
        #pragma unroll
        for (int it = 0; it < 4; ++it) {
            int idx = tid + it * 256;
            int row = idx >> 4, ch = idx & 15;
            cp16(s_base + (uint32_t)((BBASE + st * BSTG + row * BSTRN + ch * 8) * 2),
                 B + (long long)(k0 + row) * ldb + n0 + ch * 8);
        }
        asm volatile("cp.async.commit_group;");
    };

    int slabs = K / 64;
    load_tiles(0, 0);
    load_tiles(1, 1);

    int rA = lane & 15, cA = (lane >> 4) << 3;
    int mi = lane >> 3, rowin = lane & 7;

    for (int s = 0; s < slabs; ++s) {
        if (s + 1 < slabs) asm volatile("cp.async.wait_group 1;");
        else               asm volatile("cp.async.wait_group 0;");
        __syncthreads();
        if (s + 2 < slabs) load_tiles(s + 2, (s + 2) % 3);

        int st = s % 3;
        uint32_t aBase = s_base + (uint32_t)(st * ASTG * 2);
        uint32_t bBase = s_base + (uint32_t)((BBASE + st * BSTG) * 2);
        #pragma unroll
        for (int kk = 0; kk < 4; ++kk) {
            uint32_t af[2][4];
            #pragma unroll
            for (int mt = 0; mt < 2; ++mt)
                ldm4(af[mt][0], af[mt][1], af[mt][2], af[mt][3],
                     aBase + (uint32_t)(((wm + mt * 16 + rA) * GSTR + kk * 16 + cA) * 2));
            #pragma unroll
            for (int p = 0; p < 4; ++p) {
                uint32_t d0, d1, d2, d3;
                ldm4t(d0, d1, d2, d3,
                      bBase + (uint32_t)(((kk * 16 + ((mi & 1) << 3) + rowin) * BSTRN
                                          + wn + p * 16 + ((mi >> 1) << 3)) * 2));
                uint32_t bA[2] = { d0, d1 };
                uint32_t bB[2] = { d2, d3 };
                #pragma unroll
                for (int mt = 0; mt < 2; ++mt) {
                    mma_f16(acc[mt][2*p],     af[mt], bA);
                    mma_f16(acc[mt][2*p + 1], af[mt], bB);
                }
            }
        }
    }

    #pragma unroll
    for (int mt = 0; mt < 2; ++mt) {
        #pragma unroll
        for (int nt = 0; nt < 8; ++nt) {
            long long row = m0 + wm + mt * 16 + r;
            int col = n0 + wn + nt * 8 + 2 * q;
            float2 v0 = make_float2(acc[mt][nt][0], acc[mt][nt][1]);
            float2 v1 = make_float2(acc[mt][nt][2], acc[mt][nt][3]);
            if (bias) {
                float2 bb = *reinterpret_cast<const float2*>(&bias[col]);
                v0.x += bb.x; v0.y += bb.y; v1.x += bb.x; v1.y += bb.y;
            }
            if (Res) {
                float2 r0 = *reinterpret_cast<const float2*>(&Res[row * ldc + col]);
                float2 r1 = *reinterpret_cast<const float2*>(&Res[(row + 8) * ldc + col]);
                v0.x += r0.x; v0.y += r0.y; v1.x += r1.x; v1.y += r1.y;
            }
            if (ACT == 1) {
                v0.x = gelu_f(v0.x); v0.y = gelu_f(v0.y);
                v1.x = gelu_f(v1.x); v1.y = gelu_f(v1.y);
            }
            if (OUTH) {
                __half* C = reinterpret_cast<__half*>(Cv);
                *reinterpret_cast<uint32_t*>(&C[row * ldc + col])       = packh2(v0.x, v0.y);
                *reinterpret_cast<uint32_t*>(&C[(row + 8) * ldc + col]) = packh2(v1.x, v1.y);
            } else {
                float* C = reinterpret_cast<float*>(Cv);
                *reinterpret_cast<float2*>(&C[row * ldc + col])       = v0;
                *reinterpret_cast<float2*>(&C[(row + 8) * ldc + col]) = v1;
            }
        }
    }
}

// ---------------- launcher ---------------------------------------------------
extern "C" void kernel_launch(void* const* d_in, const int* in_sizes, int n_in,
                              void* d_out, int out_size) {
    const float* x     = (const float*)d_in[0];
    const float* Wq    = (const float*)d_in[1];
    const float* bq    = (const float*)d_in[2];
    const float* Wk    = (const float*)d_in[3];
    const float* bk    = (const float*)d_in[4];
    const float* Wv    = (const float*)d_in[5];
    const float* bv    = (const float*)d_in[6];
    const float* Wo    = (const float*)d_in[7];
    const float* bo    = (const float*)d_in[8];
    const float* g1    = (const float*)d_in[9];
    const float* beta1 = (const float*)d_in[10];
    const float* g2    = (const float*)d_in[11];
    const float* beta2 = (const float*)d_in[12];
    const float* W1    = (const float*)d_in[13];
    const float* c1    = (const float*)d_in[14];
    const float* W2    = (const float*)d_in[15];
    const float* c2    = (const float*)d_in[16];
    float* out = (float*)d_out;

    __half *xn, *qkv, *ctx, *hb, *Wqkv16, *Wo16, *W116, *W216;
    float *x1, *bqkv;
    cudaGetSymbolAddress((void**)&xn,     g_xn);
    cudaGetSymbolAddress((void**)&qkv,    g_qkv);
    cudaGetSymbolAddress((void**)&ctx,    g_ctx);
    cudaGetSymbolAddress((void**)&x1,     g_x1);
    cudaGetSymbolAddress((void**)&hb,     g_h);
    cudaGetSymbolAddress((void**)&Wqkv16, g_Wqkv);
    cudaGetSymbolAddress((void**)&bqkv,   g_bqkv);
    cudaGetSymbolAddress((void**)&Wo16,   g_Wo);
    cudaGetSymbolAddress((void**)&W116,   g_W1);
    cudaGetSymbolAddress((void**)&W216,   g_W2);

    static bool attr_done = false;
    static cudaStream_t s1 = nullptr, s2 = nullptr;
    static cudaEvent_t eF1, eF2, eJ1, eJ2;
    if (!attr_done) {
        cudaFuncSetAttribute((const void*)mma_gemm<0,1>,
                             cudaFuncAttributeMaxDynamicSharedMemorySize, SM_DENSE);
        cudaFuncSetAttribute((const void*)mma_gemm<0,0>,
                             cudaFuncAttributeMaxDynamicSharedMemorySize, SM_DENSE);
        cudaFuncSetAttribute((const void*)mma_gemm<1,1>,
                             cudaFuncAttributeMaxDynamicSharedMemorySize, SM_DENSE);
        cudaFuncSetAttribute((const void*)flash_k,
                             cudaFuncAttributeMaxDynamicSharedMemorySize, SM_FLASH);
        cudaStreamCreateWithFlags(&s1, cudaStreamNonBlocking);
        cudaStreamCreateWithFlags(&s2, cudaStreamNonBlocking);
        cudaEventCreateWithFlags(&eF1, cudaEventDisableTiming);
        cudaEventCreateWithFlags(&eF2, cudaEventDisableTiming);
        cudaEventCreateWithFlags(&eJ1, cudaEventDisableTiming);
        cudaEventCreateWithFlags(&eJ2, cudaEventDisableTiming);
        attr_done = true;
    }

    // 0) weight prep, forked onto side streams (capture-safe fork-join)
    cudaEventRecord(eF1, 0);
    cudaStreamWaitEvent(s1, eF1, 0);
    repack16_k<<<(HH * EE * DD + 255) / 256, 256, 0, s1>>>(
        Wq, Wk, Wv, bq, bk, bv, Wqkv16, bqkv);
    cudaEventRecord(eJ1, s1);

    cudaEventRecord(eF2, 0);
    cudaStreamWaitEvent(s2, eF2, 0);
    cvt16_k<<<(EE*EE/8  + 255) / 256, 256, 0, s2>>>(Wo, Wo16, EE*EE/8);
    cvt16_k<<<(EE*FFF/8 + 255) / 256, 256, 0, s2>>>(W1, W116, EE*FFF/8);
    cvt16_k<<<(FFF*EE/8 + 255) / 256, 256, 0, s2>>>(W2, W216, FFF*EE/8);
    cudaEventRecord(eJ2, s2);

    // 1) LN1 -> fp16 (parallel with prep)
    layernorm_k<<<MM, 256>>>(x, g1, beta1, xn);

    // join repack before QKV
    cudaStreamWaitEvent(0, eJ1, 0);

    // 2) QKV projection -> fp16 (q pre-scaled by QSCALE via Wq/bq)
    mma_gemm<0,1><<<dim3(3*EE/128, MM/128), 256, SM_DENSE>>>(
        xn, Wqkv16, bqkv, nullptr, qkv, EE, 3*EE, 3*EE);

    // 3) flash attention -> ctx (fp16)
    flash_k<<<dim3(SS/128, BB*HH), 256, SM_FLASH>>>(qkv, ctx);

    // join converts before they are consumed
    cudaStreamWaitEvent(0, eJ2, 0);

    // 4) out-proj + bias + residual -> x1 (f32)
    mma_gemm<0,0><<<dim3(EE/128, MM/128), 256, SM_DENSE>>>(
        ctx, Wo16, bo, x, x1, EE, EE, EE);

    // 5) LN2 -> fp16
    layernorm_k<<<MM, 256>>>(x1, g2, beta2, xn);

    // 6) MLP up + fast GELU -> fp16
    mma_gemm<1,1><<<dim3(FFF/128, MM/128), 256, SM_DENSE>>>(
        xn, W116, c1, nullptr, hb, EE, FFF, FFF);

    // 7) MLP down + bias + residual -> d_out (f32)
    mma_gemm<0,0><<<dim3(EE/128, MM/128), 256, SM_DENSE>>>(
        hb, W216, c2, x1, out, FFF, EE, EE);
}